// round 2
// baseline (speedup 1.0000x reference)
#include <cuda_runtime.h>

#define DT 0.1f
#define EPSF 1e-6f

__global__ void __launch_bounds__(256) econ_step_kernel(
    const float* __restrict__ need_prev,
    const float* __restrict__ inventory,   // (R, J)
    const float* __restrict__ endowment,   // (R, J)
    const float* __restrict__ price,       // (J, R)
    const float* __restrict__ pool_atp,
    const float* __restrict__ pool_adp,
    const float* __restrict__ pool_amp,
    const float* __restrict__ greed,
    const float* __restrict__ innovation,  // (R, J)
    const float* __restrict__ extraction,  // (R, M)
    const float* __restrict__ deposits,    // (R, M)
    const float* __restrict__ exergy_price,
    const float* __restrict__ bases,       // (3,)
    const float* __restrict__ scales,      // (3,)
    float* __restrict__ out,               // [0,R): gdp, [R,2R): aec
    int R)
{
    const int J = 64;
    const int M = 32;
    const int stride = gridDim.x * blockDim.x;

    for (int i = blockIdx.x * blockDim.x + threadIdx.x; i < R; i += stride) {

        // ---- energy pools / aec ----
        const float adp0 = pool_adp[i];
        const float recharge = fminf(adp0, need_prev[i] * DT);
        const float atp = pool_atp[i] + recharge;
        const float adp = adp0 - recharge;
        const float amp = pool_amp[i];
        const float aec = (atp + 0.5f * adp) / (atp + adp + amp + EPSF);

        // ---- budget fractions (frac0 feeds only dead consumption path) ----
        const float g  = greed[i];
        const float innov_f = fminf(fmaxf(bases[1] + scales[1] * g, 0.0f), 0.9f);
        const float stor_f  = fminf(fmaxf(bases[2] + scales[2] * g, 0.0f), 0.9f);

        const float wealth = atp;                       // atp_book before spends
        float atp_book = wealth - wealth * (innov_f + stor_f);
        const float innov_budget = wealth * innov_f * (1.0f / 64.0f);

        // ---- extraction (M loop) ----
        const float4* ex4 = reinterpret_cast<const float4*>(extraction + (size_t)i * M);
        const float4* dp4 = reinterpret_cast<const float4*>(deposits   + (size_t)i * M);
        float qsum = 0.0f;
#pragma unroll
        for (int m = 0; m < M / 4; ++m) {
            const float4 e = ex4[m];
            const float4 d = dp4[m];
            qsum += e.x * d.x + e.y * d.y + e.z * d.z + e.w * d.w;
        }
        qsum *= DT;                                     // q.sum before scaling
        const float cost  = qsum * 0.5f;
        const float scale = fminf(fmaxf(atp_book / (cost + EPSF), 0.0f), 1.0f);
        const float q_scaled_sum = qsum * scale;
        atp_book -= scale * cost;

        // ---- production (J loop): rate.sum and (rate*price_t).sum ----
        const float4* inv4 = reinterpret_cast<const float4*>(inventory  + (size_t)i * J);
        const float4* en4  = reinterpret_cast<const float4*>(endowment  + (size_t)i * J);
        const float4* in4  = reinterpret_cast<const float4*>(innovation + (size_t)i * J);
        const float* pcol = price + i;                  // column i of (J, R)

        const float c = 0.1f * DT * aec;
        float rate_sum = 0.0f;
        float rp_sum   = 0.0f;

#pragma unroll
        for (int jj = 0; jj < J / 4; ++jj) {
            const float4 inv = inv4[jj];
            const float4 en  = en4[jj];
            const float4 nn  = in4[jj];
            const float* pj = pcol + (size_t)(jj * 4) * R;
            const float p0 = pj[0];
            const float p1 = pj[(size_t)R];
            const float p2 = pj[(size_t)2 * R];
            const float p3 = pj[(size_t)3 * R];

            {
                const float iv = fmaxf(inv.x + DT * en.x, 0.0f);
                const float innov_new = nn.x + 0.005f * __fdividef(innov_budget, 1.0f + nn.x);
                const float r = c * innov_new * iv;
                rate_sum += r;
                rp_sum   += r * p0;
            }
            {
                const float iv = fmaxf(inv.y + DT * en.y, 0.0f);
                const float innov_new = nn.y + 0.005f * __fdividef(innov_budget, 1.0f + nn.y);
                const float r = c * innov_new * iv;
                rate_sum += r;
                rp_sum   += r * p1;
            }
            {
                const float iv = fmaxf(inv.z + DT * en.z, 0.0f);
                const float innov_new = nn.z + 0.005f * __fdividef(innov_budget, 1.0f + nn.z);
                const float r = c * innov_new * iv;
                rate_sum += r;
                rp_sum   += r * p2;
            }
            {
                const float iv = fmaxf(inv.w + DT * en.w, 0.0f);
                const float innov_new = nn.w + 0.005f * __fdividef(innov_budget, 1.0f + nn.w);
                const float r = c * innov_new * iv;
                rate_sum += r;
                rp_sum   += r * p3;
            }
        }

        const float pcost  = rate_sum * 0.3f;
        const float pscale = fminf(fmaxf(atp_book / (pcost + EPSF), 0.0f), 1.0f);

        // ---- exergy price update (depends only on aec) ----
        float ep = exergy_price[i] * (1.0f + 0.02f * (0.5f - aec));
        ep = fminf(fmaxf(ep, 1e-4f), 1e4f);

        const float gdp = pscale * rp_sum + q_scaled_sum * ep;

        out[i]     = gdp;
        out[R + i] = aec;
    }
}

extern "C" void kernel_launch(void* const* d_in, const int* in_sizes, int n_in,
                              void* d_out, int out_size) {
    // Input order per metadata: need_prev, inventory, endowment, price,
    // pool_atp, pool_adp, pool_amp, population, greed, innovation,
    // extraction_eff, deposits, emit_sink, sink_state, sink_price,
    // exergy_price, storage_cap, bases, scales
    const float* need_prev    = (const float*)d_in[0];
    const float* inventory    = (const float*)d_in[1];
    const float* endowment    = (const float*)d_in[2];
    const float* price        = (const float*)d_in[3];
    const float* pool_atp     = (const float*)d_in[4];
    const float* pool_adp     = (const float*)d_in[5];
    const float* pool_amp     = (const float*)d_in[6];
    const float* greed        = (const float*)d_in[8];
    const float* innovation   = (const float*)d_in[9];
    const float* extraction   = (const float*)d_in[10];
    const float* deposits     = (const float*)d_in[11];
    const float* exergy_price = (const float*)d_in[15];
    const float* bases        = (const float*)d_in[17];
    const float* scales       = (const float*)d_in[18];
    float* out = (float*)d_out;

    const int R = in_sizes[0];
    const int threads = 256;
    const int blocks = (R + threads - 1) / threads;
    econ_step_kernel<<<blocks, threads>>>(
        need_prev, inventory, endowment, price,
        pool_atp, pool_adp, pool_amp, greed,
        innovation, extraction, deposits, exergy_price,
        bases, scales, out, R);
}